// round 11
// baseline (speedup 1.0000x reference)
#include <cuda_runtime.h>

// Problem dimensions (fixed by the reference setup)
#define BB 4
#define LL 4096
#define DD 128
#define NN 16
#define TT 32               // chunk length
#define NC (LL / TT)        // 128 chunks per batch
#define DT_OFF 0.1f
#define FUSED_GRID (BB * NC)   // 512 blocks, one per (b, chunk)
#define SXP 132             // padded x-tile row stride (floats)

typedef unsigned long long u64;

// Scratch (device globals — no allocation allowed)
__device__ __align__(16) float g_coef[BB * LL * 48];      // fallback path only
__device__ __align__(16) float g_E[BB * NC * DD * NN];    // chunk-local end states
__device__ __align__(16) float g_H0[BB * NC * DD * NN];   // carry-in state per chunk
__device__ float g_P[BB * NC * NN];                        // chunk decay products

// grid barrier state (gen is monotonic across graph replays; count self-resets)
__device__ unsigned g_bar_count = 0;
__device__ volatile unsigned g_bar_gen = 0;

// ---------------- packed f32x2 helpers ----------------
__device__ __forceinline__ u64 fma2(u64 a, u64 b, u64 c) {
    u64 d; asm("fma.rn.f32x2 %0, %1, %2, %3;" : "=l"(d) : "l"(a), "l"(b), "l"(c));
    return d;
}
__device__ __forceinline__ u64 mul2(u64 a, u64 b) {
    u64 d; asm("mul.rn.f32x2 %0, %1, %2;" : "=l"(d) : "l"(a), "l"(b));
    return d;
}
__device__ __forceinline__ u64 pack2(float lo, float hi) {
    u64 d;
    asm("mov.b64 %0, {%1, %2};" : "=l"(d)
        : "r"(__float_as_uint(lo)), "r"(__float_as_uint(hi)));
    return d;
}
__device__ __forceinline__ float2 unpack2(u64 v) {
    unsigned int lo, hi;
    asm("mov.b64 {%0, %1}, %2;" : "=r"(lo), "=r"(hi) : "l"(v));
    return make_float2(__uint_as_float(lo), __uint_as_float(hi));
}

// ---------------- device-wide sense barrier ----------------
// Arrivals: one atomicAdd per block (pipelined RMW, ~0.85 cyc/op).
// Waiting: plain VOLATILE loads of the generation word — reads to one L2
// line are broadcast-served, they do NOT serialize the atomic unit the way
// atomicAdd(ptr,0) polling does (the R9 failure mode).
__device__ __forceinline__ void grid_barrier()
{
    __syncthreads();                       // block-local: everyone done
    if (threadIdx.x == 0) {
        __threadfence();                   // publish this block's writes
        unsigned gen = g_bar_gen;          // read BEFORE arriving
        unsigned t = atomicAdd(&g_bar_count, 1u);
        if (t == gridDim.x - 1) {
            g_bar_count = 0u;              // safe: all arrived, none re-arm yet
            __threadfence();               // reset visible before release
            atomicExch((unsigned*)&g_bar_gen, gen + 1u);
        } else {
            while (g_bar_gen == gen) __nanosleep(128);
        }
        __threadfence();                   // acquire: see other blocks' writes
    }
    __syncthreads();
}

// ===========================================================================
// FUSED persistent kernel: one block per (b, chunk).
//   Phase A: W+x -> smem, projection GEMM -> coef in smem, zero-init scan -> E,P
//   barrier
//   Phase B: inter-chunk combine, PERFECTLY BALANCED: block (b,c) combines
//            state row d=c for all n (threads 0..15), serial over 128 chunks
//   barrier
//   Phase C: re-scan with carry-in using smem-resident coef + x -> y
// ===========================================================================
__global__ __launch_bounds__(128, 4) void fused_s6(
    const float* __restrict__ x,
    const float* __restrict__ A,
    const float* __restrict__ Wb, const float* __restrict__ bb,
    const float* __restrict__ Wc, const float* __restrict__ bc,
    const float* __restrict__ Wd, const float* __restrict__ bd,
    float* __restrict__ y)
{
    __shared__ __align__(16) float sW[33 * 128];   // 16896 B
    __shared__ __align__(16) float sx[TT * SXP];   // 16896 B (padded rows)
    __shared__ __align__(16) float sc[TT * 48];    //  6144 B
    __shared__ float sb[33];
    __shared__ float sA[16];

    int tid = threadIdx.x;
    int blk = blockIdx.x;
    int c = blk & (NC - 1);
    int b = blk >> 7;                 // NC = 128

    // ---- load W / biases / A into smem ----
    for (int i = tid; i < 2048; i += 128) {
        sW[i]        = Wb[i];
        sW[2048 + i] = Wc[i];
    }
    sW[4096 + tid] = Wd[tid];
    if (tid < 16) { sb[tid] = bb[tid]; sb[16 + tid] = bc[tid]; sA[tid] = A[tid]; }
    if (tid == 0) sb[32] = bd[0];

    // ---- load x tile (TT x 128) into padded smem ----
    const float4* xg = (const float4*)(x + (size_t)(b * LL + c * TT) * DD);
#pragma unroll
    for (int i = 0; i < 8; i++) {
        int idx = i * 128 + tid;          // float4 index, 1024 total
        float4 v = xg[idx];
        int t   = idx >> 5;               // 32 float4 per row
        int col = (idx & 31) << 2;
        *(float4*)&sx[t * SXP + col] = v;
    }
    __syncthreads();

    // ---- projection GEMM: 4 threads per position, kk-rotation (bank-safe) ----
    {
        int pl = tid >> 2;                // position within chunk, 0..31
        int q  = tid & 3;                 // quarter of the 128-dim dot

        float acc[33];
#pragma unroll
        for (int j = 0; j < 33; j++) acc[j] = 0.f;

        const float4* xr = (const float4*)(sx + pl * SXP + q * 32);
        const float4* W4 = (const float4*)sW;

#pragma unroll
        for (int kk = 0; kk < 8; kk++) {
            int kkr = (kk + 2 * q) & 7;   // rotate -> conflict-free W banks
            float4 xv = xr[kkr];
            int basei = q * 8 + kkr;
#pragma unroll
            for (int j = 0; j < 33; j++) {
                float4 wv = W4[j * 32 + basei];
                acc[j] = fmaf(xv.w, wv.w, fmaf(xv.z, wv.z,
                         fmaf(xv.y, wv.y, fmaf(xv.x, wv.x, acc[j]))));
            }
        }
#pragma unroll
        for (int j = 0; j < 33; j++) {
            acc[j] += __shfl_down_sync(0xffffffffu, acc[j], 2);
            acc[j] += __shfl_down_sync(0xffffffffu, acc[j], 1);
        }

        if (q == 0) {
            float z = acc[32] + sb[32];
            float delta = fmaxf(z, 0.f) + log1pf(expf(-fabsf(z))) + DT_OFF;
            float* row = sc + pl * 48;
#pragma unroll
            for (int n = 0; n < 16; n++) {
                float da = delta * sA[n];
                row[n]      = expf(da);
                row[16 + n] = (1.0f - expf(-da)) * delta * (acc[n] + sb[n]);
                row[32 + n] = acc[16 + n] + sb[16 + n];
            }
        }
    }
    __syncthreads();

    // ---- Phase A: zero-init chunk scan -> E, P ----
    {
        int d = tid;
        u64 h[8];
#pragma unroll
        for (int i = 0; i < 8; i++) h[i] = 0ull;

#pragma unroll 4
        for (int t = 0; t < TT; t++) {
            float xt = sx[t * SXP + d];
            u64 x2 = pack2(xt, xt);
            const ulonglong2* row = (const ulonglong2*)(sc + t * 48);
#pragma unroll
            for (int i = 0; i < 4; i++) {
                ulonglong2 e2 = row[i];
                ulonglong2 w2 = row[4 + i];
                h[2 * i]     = fma2(e2.x, h[2 * i],     mul2(w2.x, x2));
                h[2 * i + 1] = fma2(e2.y, h[2 * i + 1], mul2(w2.y, x2));
            }
        }

        ulonglong2* Eo = (ulonglong2*)(g_E + (size_t)((b * NC + c) * DD + d) * NN);
#pragma unroll
        for (int i = 0; i < 4; i++) {
            ulonglong2 v; v.x = h[2 * i]; v.y = h[2 * i + 1];
            Eo[i] = v;
        }
        if (d < 16) {
            float p = 1.f;
#pragma unroll
            for (int t = 0; t < TT; t++) p *= sc[t * 48 + d];
            g_P[(b * NC + c) * NN + d] = p;
        }
    }

    grid_barrier();

    // ---- Phase B: balanced inter-chunk combine ----
    // Block (b,c) owns state row d=c of batch b; threads 0..15 = n.
    // Serial over all NC chunks:  H0[cc] = h;  h = P[cc]*h + E[cc].
    if (tid < NN) {
        int n = tid;
        float h = 0.f;
        const float* P = g_P + b * NC * NN + n;
        size_t o = (size_t)b * NC * (DD * NN) + c * NN + n;
#pragma unroll 16
        for (int cc = 0; cc < NC; cc++) {
            g_H0[o] = h;
            h = fmaf(__ldcg(P + cc * NN), h, __ldcg(g_E + o));
            o += DD * NN;
        }
    }

    grid_barrier();

    // ---- Phase C: carry-in scan using smem-resident coef + x -> y ----
    {
        int d = tid;
        u64 h[8];
        const uint4* hi = (const uint4*)(g_H0 + (size_t)((b * NC + c) * DD + d) * NN);
#pragma unroll
        for (int i = 0; i < 4; i++) {
            uint4 v = __ldcg(hi + i);
            h[2 * i]     = pack2(__uint_as_float(v.x), __uint_as_float(v.y));
            h[2 * i + 1] = pack2(__uint_as_float(v.z), __uint_as_float(v.w));
        }

        float* yp = y + (size_t)(b * LL + c * TT) * DD + d;

#pragma unroll 4
        for (int t = 0; t < TT; t++) {
            float xt = sx[t * SXP + d];
            u64 x2 = pack2(xt, xt);
            const ulonglong2* row = (const ulonglong2*)(sc + t * 48);

            u64 a0 = 0ull, a1 = 0ull, a2 = 0ull, a3 = 0ull;
#pragma unroll
            for (int i = 0; i < 4; i++) {
                ulonglong2 e2 = row[i];
                ulonglong2 w2 = row[4 + i];
                ulonglong2 c2 = row[8 + i];
                h[2 * i]     = fma2(e2.x, h[2 * i],     mul2(w2.x, x2));
                h[2 * i + 1] = fma2(e2.y, h[2 * i + 1], mul2(w2.y, x2));
                if (i == 0)      { a0 = fma2(c2.x, h[0], a0); a1 = fma2(c2.y, h[1], a1); }
                else if (i == 1) { a2 = fma2(c2.x, h[2], a2); a3 = fma2(c2.y, h[3], a3); }
                else if (i == 2) { a0 = fma2(c2.x, h[4], a0); a1 = fma2(c2.y, h[5], a1); }
                else             { a2 = fma2(c2.x, h[6], a2); a3 = fma2(c2.y, h[7], a3); }
            }
            float2 p0 = unpack2(a0), p1 = unpack2(a1), p2 = unpack2(a2), p3 = unpack2(a3);
            yp[t * DD] = ((p0.x + p0.y) + (p1.x + p1.y)) + ((p2.x + p2.y) + (p3.x + p3.y));
        }
    }
}

// ===========================================================================
// Fallback path (proven 4-kernel pipeline) — used only if the fused kernel
// cannot be fully co-resident on this device.
// ===========================================================================
__global__ __launch_bounds__(128) void k1_coef(
    const float* __restrict__ x,
    const float* __restrict__ A,
    const float* __restrict__ Wb, const float* __restrict__ bb,
    const float* __restrict__ Wc, const float* __restrict__ bc,
    const float* __restrict__ Wd, const float* __restrict__ bd)
{
    __shared__ __align__(16) float sW[33 * 128];
    __shared__ float sb[33];
    __shared__ float sA[16];

    int tid = threadIdx.x;
    for (int i = tid; i < 2048; i += 128) {
        sW[i]        = Wb[i];
        sW[2048 + i] = Wc[i];
    }
    sW[4096 + tid] = Wd[tid];
    if (tid < 16) { sb[tid] = bb[tid]; sb[16 + tid] = bc[tid]; sA[tid] = A[tid]; }
    if (tid == 0) sb[32] = bd[0];
    __syncthreads();

    int g   = blockIdx.x * 128 + tid;
    int pos = g >> 2;
    int q   = g & 3;

    float acc[33];
#pragma unroll
    for (int j = 0; j < 33; j++) acc[j] = 0.f;

    const float4* xr = (const float4*)(x + (size_t)pos * DD + q * 32);
    const float4* W4 = (const float4*)sW;

#pragma unroll
    for (int kk = 0; kk < 8; kk++) {
        int kkr = (kk + 2 * q) & 7;
        float4 xv = xr[kkr];
        int basei = q * 8 + kkr;
#pragma unroll
        for (int j = 0; j < 33; j++) {
            float4 wv = W4[j * 32 + basei];
            acc[j] = fmaf(xv.w, wv.w, fmaf(xv.z, wv.z,
                     fmaf(xv.y, wv.y, fmaf(xv.x, wv.x, acc[j]))));
        }
    }
#pragma unroll
    for (int j = 0; j < 33; j++) {
        acc[j] += __shfl_down_sync(0xffffffffu, acc[j], 2);
        acc[j] += __shfl_down_sync(0xffffffffu, acc[j], 1);
    }

    if (q == 0) {
        float z = acc[32] + sb[32];
        float delta = fmaxf(z, 0.f) + log1pf(expf(-fabsf(z))) + DT_OFF;
        float out[48];
#pragma unroll
        for (int n = 0; n < 16; n++) {
            float da = delta * sA[n];
            out[n]      = expf(da);
            out[16 + n] = (1.0f - expf(-da)) * delta * (acc[n] + sb[n]);
            out[32 + n] = acc[16 + n] + sb[16 + n];
        }
        float4* o = (float4*)(g_coef + (size_t)pos * 48);
        const float4* ov = (const float4*)out;
#pragma unroll
        for (int i = 0; i < 12; i++) o[i] = ov[i];
    }
}

__global__ __launch_bounds__(128) void k2_local(const float* __restrict__ x)
{
    __shared__ __align__(16) float sc[TT * 48];
    int c = blockIdx.x, b = blockIdx.y, d = threadIdx.x;

    float xv[TT];
    const float* xp = x + (size_t)(b * LL + c * TT) * DD + d;
#pragma unroll
    for (int t = 0; t < TT; t++) xv[t] = xp[t * DD];

    const float4* csrc = (const float4*)(g_coef + (size_t)(b * LL + c * TT) * 48);
    float4* cdst = (float4*)sc;
#pragma unroll
    for (int i = 0; i < 3; i++) cdst[d + 128 * i] = csrc[d + 128 * i];
    __syncthreads();

    u64 h[8];
#pragma unroll
    for (int i = 0; i < 8; i++) h[i] = 0ull;

#pragma unroll 4
    for (int t = 0; t < TT; t++) {
        u64 x2 = pack2(xv[t], xv[t]);
        const ulonglong2* row = (const ulonglong2*)(sc + t * 48);
#pragma unroll
        for (int i = 0; i < 4; i++) {
            ulonglong2 e2 = row[i];
            ulonglong2 w2 = row[4 + i];
            h[2 * i]     = fma2(e2.x, h[2 * i],     mul2(w2.x, x2));
            h[2 * i + 1] = fma2(e2.y, h[2 * i + 1], mul2(w2.y, x2));
        }
    }

    ulonglong2* Eo = (ulonglong2*)(g_E + (size_t)((b * NC + c) * DD + d) * NN);
#pragma unroll
    for (int i = 0; i < 4; i++) {
        ulonglong2 v; v.x = h[2 * i]; v.y = h[2 * i + 1];
        Eo[i] = v;
    }
    if (d < 16) {
        float p = 1.f;
#pragma unroll
        for (int t = 0; t < TT; t++) p *= sc[t * 48 + d];
        g_P[(b * NC + c) * NN + d] = p;
    }
}

__global__ __launch_bounds__(128) void k25_combine()
{
    int idx = blockIdx.x * 128 + threadIdx.x;
    int b = idx >> 11;
    int r = idx & 2047;
    int n = r & 15;
    float h = 0.f;
    const float* __restrict__ P = g_P + b * NC * NN + n;
    size_t o = (size_t)b * NC * (DD * NN) + r;
#pragma unroll 16
    for (int c = 0; c < NC; c++) {
        g_H0[o] = h;
        h = fmaf(P[c * NN], h, g_E[o]);
        o += DD * NN;
    }
}

__global__ __launch_bounds__(128) void k3_scan(const float* __restrict__ x,
                                               float* __restrict__ y)
{
    __shared__ __align__(16) float sc[TT * 48];
    int c = blockIdx.x, b = blockIdx.y, d = threadIdx.x;

    float xv[TT];
    const float* xp = x + (size_t)(b * LL + c * TT) * DD + d;
#pragma unroll
    for (int t = 0; t < TT; t++) xv[t] = xp[t * DD];

    const float4* csrc = (const float4*)(g_coef + (size_t)(b * LL + c * TT) * 48);
    float4* cdst = (float4*)sc;
#pragma unroll
    for (int i = 0; i < 3; i++) cdst[d + 128 * i] = csrc[d + 128 * i];

    u64 h[8];
    const ulonglong2* hi = (const ulonglong2*)(g_H0 + (size_t)((b * NC + c) * DD + d) * NN);
#pragma unroll
    for (int i = 0; i < 4; i++) {
        ulonglong2 v = hi[i];
        h[2 * i] = v.x; h[2 * i + 1] = v.y;
    }
    __syncthreads();

    float* yp = y + (size_t)(b * LL + c * TT) * DD + d;

#pragma unroll 4
    for (int t = 0; t < TT; t++) {
        u64 x2 = pack2(xv[t], xv[t]);
        const ulonglong2* row = (const ulonglong2*)(sc + t * 48);

        u64 a0 = 0ull, a1 = 0ull, a2 = 0ull, a3 = 0ull;
#pragma unroll
        for (int i = 0; i < 4; i++) {
            ulonglong2 e2 = row[i];
            ulonglong2 w2 = row[4 + i];
            ulonglong2 c2 = row[8 + i];
            h[2 * i]     = fma2(e2.x, h[2 * i],     mul2(w2.x, x2));
            h[2 * i + 1] = fma2(e2.y, h[2 * i + 1], mul2(w2.y, x2));
            if (i == 0)      { a0 = fma2(c2.x, h[0], a0); a1 = fma2(c2.y, h[1], a1); }
            else if (i == 1) { a2 = fma2(c2.x, h[2], a2); a3 = fma2(c2.y, h[3], a3); }
            else if (i == 2) { a0 = fma2(c2.x, h[4], a0); a1 = fma2(c2.y, h[5], a1); }
            else             { a2 = fma2(c2.x, h[6], a2); a3 = fma2(c2.y, h[7], a3); }
        }
        float2 p0 = unpack2(a0), p1 = unpack2(a1), p2 = unpack2(a2), p3 = unpack2(a3);
        yp[t * DD] = ((p0.x + p0.y) + (p1.x + p1.y)) + ((p2.x + p2.y) + (p3.x + p3.y));
    }
}

// ---------------------------------------------------------------------------
extern "C" void kernel_launch(void* const* d_in, const int* in_sizes, int n_in,
                              void* d_out, int out_size)
{
    const float* x  = (const float*)d_in[0];
    const float* A  = (const float*)d_in[1];
    const float* Wb = (const float*)d_in[2];
    const float* bb = (const float*)d_in[3];
    const float* Wc = (const float*)d_in[4];
    const float* bc = (const float*)d_in[5];
    const float* Wd = (const float*)d_in[6];
    const float* bd = (const float*)d_in[7];
    float* y = (float*)d_out;

    // The fused kernel's grid barrier requires all FUSED_GRID blocks to be
    // co-resident. Verify via the occupancy API; otherwise use the safe path.
    int dev = 0, nsm = 0, maxb = 0;
    cudaGetDevice(&dev);
    cudaDeviceGetAttribute(&nsm, cudaDevAttrMultiProcessorCount, dev);
    cudaOccupancyMaxActiveBlocksPerMultiprocessor(&maxb, fused_s6, 128, 0);

    if ((long long)nsm * maxb >= FUSED_GRID) {
        fused_s6<<<FUSED_GRID, 128>>>(x, A, Wb, bb, Wc, bc, Wd, bd, y);
    } else {
        k1_coef<<<512, 128>>>(x, A, Wb, bb, Wc, bc, Wd, bd);
        dim3 grid(NC, BB);
        k2_local<<<grid, 128>>>(x);
        k25_combine<<<64, 128>>>();
        k3_scan<<<grid, 128>>>(x, y);
    }
}

// round 12
// speedup vs baseline: 1.3838x; 1.3838x over previous
#include <cuda_runtime.h>

// Problem dimensions (fixed by the reference setup)
#define BB 4
#define LL 4096
#define DD 128
#define NN 16
#define TT 32               // chunk length
#define NC (LL / TT)        // 128 chunks per batch
#define NG 16               // super-groups per batch (hierarchical combine)
#define GC 8                // chunks per super-group (NG*GC == NC)
#define DT_OFF 0.1f

typedef unsigned long long u64;

// Scratch (device globals — no allocation allowed)
__device__ __align__(16) float g_coef[BB * LL * 48];        // per-(b,l): e[16],w[16],C[16]
__device__ __align__(16) float g_E[BB * NC * DD * NN];      // chunk-local end states
__device__ __align__(16) float g_H0[BB * NC * DD * NN];     // carry-in state per chunk
__device__ float g_P[BB * NC * NN];                          // chunk decay products
__device__ __align__(16) float g_E2[BB * NG * DD * NN];     // group-composed E
__device__ float g_P2[BB * NG * NN];                         // group-composed P
__device__ __align__(16) float g_H0g[BB * NG * DD * NN];    // group carry-ins

// ---------------- packed f32x2 helpers ----------------
__device__ __forceinline__ u64 fma2(u64 a, u64 b, u64 c) {
    u64 d; asm("fma.rn.f32x2 %0, %1, %2, %3;" : "=l"(d) : "l"(a), "l"(b), "l"(c));
    return d;
}
__device__ __forceinline__ u64 mul2(u64 a, u64 b) {
    u64 d; asm("mul.rn.f32x2 %0, %1, %2;" : "=l"(d) : "l"(a), "l"(b));
    return d;
}
__device__ __forceinline__ u64 pack2(float lo, float hi) {
    u64 d;
    asm("mov.b64 %0, {%1, %2};" : "=l"(d)
        : "r"(__float_as_uint(lo)), "r"(__float_as_uint(hi)));
    return d;
}
__device__ __forceinline__ float2 unpack2(u64 v) {
    unsigned int lo, hi;
    asm("mov.b64 {%0, %1}, %2;" : "=r"(lo), "=r"(hi) : "l"(v));
    return make_float2(__uint_as_float(lo), __uint_as_float(hi));
}

// ---------------------------------------------------------------------------
// K1: per-(b,l) coefficients. 33 length-128 dot products per position.
// 64-thread blocks, 16 positions/block, 4 threads per position (quarter dots,
// kk-rotation for conflict-free W banks). Butterfly shfl gives ALL 4 threads
// the full sums; each thread then produces 4 of the 16 n-coefficients
// (distributes the MUFU exp work 4x wider than a q==0-only epilogue).
// ---------------------------------------------------------------------------
__global__ __launch_bounds__(64) void k1_coef(
    const float* __restrict__ x,
    const float* __restrict__ A,
    const float* __restrict__ Wb, const float* __restrict__ bb,
    const float* __restrict__ Wc, const float* __restrict__ bc,
    const float* __restrict__ Wd, const float* __restrict__ bd)
{
    __shared__ __align__(16) float sW[33 * 128];
    __shared__ float sb[33];
    __shared__ float sA[16];

    int tid = threadIdx.x;
    for (int i = tid; i < 2048; i += 64) {
        sW[i]        = Wb[i];
        sW[2048 + i] = Wc[i];
    }
    for (int i = tid; i < 128; i += 64) sW[4096 + i] = Wd[i];
    if (tid < 16) { sb[tid] = bb[tid]; sb[16 + tid] = bc[tid]; sA[tid] = A[tid]; }
    if (tid == 0) sb[32] = bd[0];
    __syncthreads();

    int pos = blockIdx.x * 16 + (tid >> 2);   // (b*L + l), 0..16383
    int q   = tid & 3;                         // quarter of the 128-dim dot

    float acc[33];
#pragma unroll
    for (int j = 0; j < 33; j++) acc[j] = 0.f;

    const float4* xr = (const float4*)(x + (size_t)pos * DD + q * 32);
    const float4* W4 = (const float4*)sW;

#pragma unroll
    for (int kk = 0; kk < 8; kk++) {
        int kkr = (kk + 2 * q) & 7;           // rotate -> conflict-free banks
        float4 xv = xr[kkr];
        int basei = q * 8 + kkr;
#pragma unroll
        for (int j = 0; j < 33; j++) {
            float4 wv = W4[j * 32 + basei];
            acc[j] = fmaf(xv.w, wv.w, fmaf(xv.z, wv.z,
                     fmaf(xv.y, wv.y, fmaf(xv.x, wv.x, acc[j]))));
        }
    }
    // butterfly: ALL four threads get the complete dots
#pragma unroll
    for (int j = 0; j < 33; j++) {
        acc[j] += __shfl_xor_sync(0xffffffffu, acc[j], 1);
        acc[j] += __shfl_xor_sync(0xffffffffu, acc[j], 2);
    }

    float z = acc[32] + sb[32];
    // stable softplus (fast exp: |err| ~1e-7, tolerance 1e-3)
    float delta = fmaxf(z, 0.f) + log1pf(__expf(-fabsf(z))) + DT_OFF;

    int n0 = q * 4;                            // this thread's 4 n's
    float4 eo, wo, co;
#pragma unroll
    for (int k = 0; k < 4; k++) {
        int n = n0 + k;
        float da = delta * sA[n];
        float e  = __expf(da);
        float em = __expf(-da);
        ((float*)&eo)[k] = e;
        ((float*)&wo)[k] = (1.0f - em) * delta * (acc[n] + sb[n]);
        ((float*)&co)[k] = acc[16 + n] + sb[16 + n];
    }
    float* o = g_coef + (size_t)pos * 48;
    *(float4*)(o + n0)      = eo;
    *(float4*)(o + 16 + n0) = wo;
    *(float4*)(o + 32 + n0) = co;
}

// ---------------------------------------------------------------------------
// K2: chunk-local scan, h=0 init. 256-thread blocks: thread = (d, n-half).
// Each thread owns 8 n's (4 f32x2 states) -> warps double vs d-only split.
// ---------------------------------------------------------------------------
__global__ __launch_bounds__(256) void k2_local(const float* __restrict__ x)
{
    __shared__ __align__(16) float sc[TT * 48];
    int c = blockIdx.x, b = blockIdx.y;
    int tid = threadIdx.x;
    int d  = tid >> 1;
    int nh = tid & 1;

    // front-batched x loads: thread's column of the chunk
    float xv[TT];
    const float* xp = x + (size_t)(b * LL + c * TT) * DD + d;
#pragma unroll
    for (int t = 0; t < TT; t++) xv[t] = xp[t * DD];

    const float4* csrc = (const float4*)(g_coef + (size_t)(b * LL + c * TT) * 48);
    float4* cdst = (float4*)sc;
    for (int i = tid; i < 384; i += 256) cdst[i] = csrc[i];
    __syncthreads();

    u64 h[4];
#pragma unroll
    for (int i = 0; i < 4; i++) h[i] = 0ull;

#pragma unroll 4
    for (int t = 0; t < TT; t++) {
        u64 x2 = pack2(xv[t], xv[t]);
        const ulonglong2* row = (const ulonglong2*)(sc + t * 48);
        ulonglong2 e2a = row[nh * 2],     e2b = row[nh * 2 + 1];
        ulonglong2 w2a = row[4 + nh * 2], w2b = row[5 + nh * 2];
        h[0] = fma2(e2a.x, h[0], mul2(w2a.x, x2));
        h[1] = fma2(e2a.y, h[1], mul2(w2a.y, x2));
        h[2] = fma2(e2b.x, h[2], mul2(w2b.x, x2));
        h[3] = fma2(e2b.y, h[3], mul2(w2b.y, x2));
    }

    ulonglong2* Eo = (ulonglong2*)(g_E + ((size_t)(b * NC + c) * DD + d) * NN + nh * 8);
    { ulonglong2 v; v.x = h[0]; v.y = h[1]; Eo[0] = v; }
    { ulonglong2 v; v.x = h[2]; v.y = h[3]; Eo[1] = v; }

    if (tid < 16) {
        float p = 1.f;
#pragma unroll
        for (int t = 0; t < TT; t++) p *= sc[t * 48 + tid];
        g_P[(b * NC + c) * NN + tid] = p;
    }
}

// ---------------------------------------------------------------------------
// K2.5a: level-1 compose. Thread (b,g,d,n) composes its GC=8 chunks into an
// affine map (P2, E2):  E' = P_c*E' + E_c ;  P' *= P_c.
// ---------------------------------------------------------------------------
__global__ __launch_bounds__(256) void k25a()
{
    int idx = blockIdx.x * 256 + threadIdx.x;   // 0..131071
    int b = idx >> 15;
    int g = (idx >> 11) & 15;
    int d = (idx >> 4) & 127;
    int n = idx & 15;

    float Pa = 1.f, Ea = 0.f;
    int c0 = g * GC;
    size_t o = ((size_t)(b * NC + c0) * DD + d) * NN + n;
    const float* P = g_P + (b * NC + c0) * NN + n;
#pragma unroll
    for (int s = 0; s < GC; s++) {
        float p = P[s * NN];
        Ea = fmaf(p, Ea, g_E[o]);
        Pa *= p;
        o += (size_t)DD * NN;
    }
    g_E2[((size_t)(b * NG + g) * DD + d) * NN + n] = Ea;
    if (d == 0) g_P2[(b * NG + g) * NN + n] = Pa;
}

// ---------------------------------------------------------------------------
// K2.5b: level-2 serial scan over the NG=16 groups -> group carry-ins H0g.
// ---------------------------------------------------------------------------
__global__ __launch_bounds__(128) void k25b()
{
    int idx = blockIdx.x * 128 + threadIdx.x;   // 0..8191
    int b = idx >> 11;
    int r = idx & 2047;                          // d*16 + n
    int n = r & 15;
    float h = 0.f;
    const float* P2 = g_P2 + b * NG * NN + n;
    size_t o = (size_t)b * NG * (DD * NN) + r;
#pragma unroll
    for (int g = 0; g < NG; g++) {
        g_H0g[o] = h;
        h = fmaf(P2[g * NN], h, g_E2[o]);
        o += DD * NN;
    }
}

// ---------------------------------------------------------------------------
// K2.5c: level-3 expand. Thread (b,g,d,n) walks its 8 chunks from the group
// carry-in, emitting per-chunk carry-ins H0.
// ---------------------------------------------------------------------------
__global__ __launch_bounds__(256) void k25c()
{
    int idx = blockIdx.x * 256 + threadIdx.x;
    int b = idx >> 15;
    int g = (idx >> 11) & 15;
    int d = (idx >> 4) & 127;
    int n = idx & 15;

    float h = g_H0g[((size_t)(b * NG + g) * DD + d) * NN + n];
    int c0 = g * GC;
    size_t o = ((size_t)(b * NC + c0) * DD + d) * NN + n;
    const float* P = g_P + (b * NC + c0) * NN + n;
#pragma unroll
    for (int s = 0; s < GC; s++) {
        g_H0[o] = h;
        h = fmaf(P[s * NN], h, g_E[o]);
        o += (size_t)DD * NN;
    }
}

// ---------------------------------------------------------------------------
// K3: final scan with carry-in; y[b,l,d] = sum_n C[l,n]*h[n].
// 256-thread blocks, thread = (d, n-half); cross-half combine via shfl.
// ---------------------------------------------------------------------------
__global__ __launch_bounds__(256) void k3_scan(const float* __restrict__ x,
                                               float* __restrict__ y)
{
    __shared__ __align__(16) float sc[TT * 48];
    int c = blockIdx.x, b = blockIdx.y;
    int tid = threadIdx.x;
    int d  = tid >> 1;
    int nh = tid & 1;

    float xv[TT];
    const float* xp = x + (size_t)(b * LL + c * TT) * DD + d;
#pragma unroll
    for (int t = 0; t < TT; t++) xv[t] = xp[t * DD];

    const float4* csrc = (const float4*)(g_coef + (size_t)(b * LL + c * TT) * 48);
    float4* cdst = (float4*)sc;
    for (int i = tid; i < 384; i += 256) cdst[i] = csrc[i];

    u64 h[4];
    const ulonglong2* hi = (const ulonglong2*)(g_H0 + ((size_t)(b * NC + c) * DD + d) * NN + nh * 8);
    { ulonglong2 v = hi[0]; h[0] = v.x; h[1] = v.y; }
    { ulonglong2 v = hi[1]; h[2] = v.x; h[3] = v.y; }
    __syncthreads();

    float* yp = y + (size_t)(b * LL + c * TT) * DD + d;

#pragma unroll 4
    for (int t = 0; t < TT; t++) {
        u64 x2 = pack2(xv[t], xv[t]);
        const ulonglong2* row = (const ulonglong2*)(sc + t * 48);
        ulonglong2 e2a = row[nh * 2],     e2b = row[nh * 2 + 1];
        ulonglong2 w2a = row[4 + nh * 2], w2b = row[5 + nh * 2];
        ulonglong2 c2a = row[8 + nh * 2], c2b = row[9 + nh * 2];

        h[0] = fma2(e2a.x, h[0], mul2(w2a.x, x2));
        h[1] = fma2(e2a.y, h[1], mul2(w2a.y, x2));
        h[2] = fma2(e2b.x, h[2], mul2(w2b.x, x2));
        h[3] = fma2(e2b.y, h[3], mul2(w2b.y, x2));

        u64 a0 = 0ull, a1 = 0ull;
        a0 = fma2(c2a.x, h[0], a0);
        a1 = fma2(c2a.y, h[1], a1);
        a0 = fma2(c2b.x, h[2], a0);
        a1 = fma2(c2b.y, h[3], a1);
        float2 p0 = unpack2(a0), p1 = unpack2(a1);
        float part = (p0.x + p0.y) + (p1.x + p1.y);
        float other = __shfl_xor_sync(0xffffffffu, part, 1);
        if (nh == 0) yp[t * DD] = part + other;
    }
}

// ---------------------------------------------------------------------------
extern "C" void kernel_launch(void* const* d_in, const int* in_sizes, int n_in,
                              void* d_out, int out_size)
{
    const float* x  = (const float*)d_in[0];
    const float* A  = (const float*)d_in[1];
    const float* Wb = (const float*)d_in[2];
    const float* bb = (const float*)d_in[3];
    const float* Wc = (const float*)d_in[4];
    const float* bc = (const float*)d_in[5];
    const float* Wd = (const float*)d_in[6];
    const float* bd = (const float*)d_in[7];
    float* y = (float*)d_out;

    k1_coef<<<1024, 64>>>(x, A, Wb, bb, Wc, bc, Wd, bd);

    dim3 grid(NC, BB);
    k2_local<<<grid, 256>>>(x);
    k25a<<<512, 256>>>();
    k25b<<<64, 128>>>();
    k25c<<<512, 256>>>();
    k3_scan<<<grid, 256>>>(x, y);
}

// round 13
// speedup vs baseline: 1.5806x; 1.1422x over previous
#include <cuda_runtime.h>

// Problem dimensions (fixed by the reference setup)
#define BB 4
#define LL 4096
#define DD 128
#define NN 16
#define TT 32               // chunk length
#define NC (LL / TT)        // 128 chunks per batch
#define DT_OFF 0.1f

typedef unsigned long long u64;

// Scratch (device globals — no allocation allowed)
__device__ __align__(16) float g_coef[BB * LL * 48];        // per-(b,l): e[16],w[16],C[16]
__device__ __align__(16) float g_Et[BB * NN * NC * DD];     // end states, TRANSPOSED [b][n][c][d]
__device__ __align__(16) float g_H0t[BB * NN * NC * DD];    // carry-ins,  TRANSPOSED [b][n][c][d]
__device__ float g_P[BB * NC * NN];                          // chunk decay products [b][c][n]

// ---------------- packed f32x2 helpers ----------------
__device__ __forceinline__ u64 fma2(u64 a, u64 b, u64 c) {
    u64 d; asm("fma.rn.f32x2 %0, %1, %2, %3;" : "=l"(d) : "l"(a), "l"(b), "l"(c));
    return d;
}
__device__ __forceinline__ u64 mul2(u64 a, u64 b) {
    u64 d; asm("mul.rn.f32x2 %0, %1, %2;" : "=l"(d) : "l"(a), "l"(b));
    return d;
}
__device__ __forceinline__ u64 pack2(float lo, float hi) {
    u64 d;
    asm("mov.b64 %0, {%1, %2};" : "=l"(d)
        : "r"(__float_as_uint(lo)), "r"(__float_as_uint(hi)));
    return d;
}
__device__ __forceinline__ float2 unpack2(u64 v) {
    unsigned int lo, hi;
    asm("mov.b64 {%0, %1}, %2;" : "=r"(lo), "=r"(hi) : "l"(v));
    return make_float2(__uint_as_float(lo), __uint_as_float(hi));
}

// ---------------------------------------------------------------------------
// K1: per-(b,l) coefficients. 33 length-128 dot products per position.
// 64-thread blocks, 16 positions/block, 4 threads per position (quarter dots,
// kk-rotation for conflict-free W banks). Butterfly shfl gives ALL 4 threads
// the full sums; each thread produces 4 of the 16 n-coefficients.
// ---------------------------------------------------------------------------
__global__ __launch_bounds__(64) void k1_coef(
    const float* __restrict__ x,
    const float* __restrict__ A,
    const float* __restrict__ Wb, const float* __restrict__ bb,
    const float* __restrict__ Wc, const float* __restrict__ bc,
    const float* __restrict__ Wd, const float* __restrict__ bd)
{
    __shared__ __align__(16) float sW[33 * 128];
    __shared__ float sb[33];
    __shared__ float sA[16];

    int tid = threadIdx.x;
    for (int i = tid; i < 2048; i += 64) {
        sW[i]        = Wb[i];
        sW[2048 + i] = Wc[i];
    }
    for (int i = tid; i < 128; i += 64) sW[4096 + i] = Wd[i];
    if (tid < 16) { sb[tid] = bb[tid]; sb[16 + tid] = bc[tid]; sA[tid] = A[tid]; }
    if (tid == 0) sb[32] = bd[0];
    __syncthreads();

    int pos = blockIdx.x * 16 + (tid >> 2);   // (b*L + l), 0..16383
    int q   = tid & 3;                         // quarter of the 128-dim dot

    float acc[33];
#pragma unroll
    for (int j = 0; j < 33; j++) acc[j] = 0.f;

    const float4* xr = (const float4*)(x + (size_t)pos * DD + q * 32);
    const float4* W4 = (const float4*)sW;

#pragma unroll
    for (int kk = 0; kk < 8; kk++) {
        int kkr = (kk + 2 * q) & 7;           // rotate -> conflict-free banks
        float4 xv = xr[kkr];
        int basei = q * 8 + kkr;
#pragma unroll
        for (int j = 0; j < 33; j++) {
            float4 wv = W4[j * 32 + basei];
            acc[j] = fmaf(xv.w, wv.w, fmaf(xv.z, wv.z,
                     fmaf(xv.y, wv.y, fmaf(xv.x, wv.x, acc[j]))));
        }
    }
    // butterfly: ALL four threads get the complete dots
#pragma unroll
    for (int j = 0; j < 33; j++) {
        acc[j] += __shfl_xor_sync(0xffffffffu, acc[j], 1);
        acc[j] += __shfl_xor_sync(0xffffffffu, acc[j], 2);
    }

    float z = acc[32] + sb[32];
    // stable softplus (fast exp: |err| ~1e-7, tolerance 1e-3)
    float delta = fmaxf(z, 0.f) + log1pf(__expf(-fabsf(z))) + DT_OFF;

    int n0 = q * 4;                            // this thread's 4 n's
    float4 eo, wo, co;
#pragma unroll
    for (int k = 0; k < 4; k++) {
        int n = n0 + k;
        float da = delta * sA[n];
        float e  = __expf(da);
        float em = __expf(-da);
        ((float*)&eo)[k] = e;
        ((float*)&wo)[k] = (1.0f - em) * delta * (acc[n] + sb[n]);
        ((float*)&co)[k] = acc[16 + n] + sb[16 + n];
    }
    float* o = g_coef + (size_t)pos * 48;
    *(float4*)(o + n0)      = eo;
    *(float4*)(o + 16 + n0) = wo;
    *(float4*)(o + 32 + n0) = co;
}

// ---------------------------------------------------------------------------
// K2: chunk-local scan, h=0 init. 256-thread blocks: thread = (d, n-half).
// Each thread owns 8 n's (4 f32x2 states). End states written TRANSPOSED
// to g_Et[b][n][c][d] (coalesced across d within each n).
// ---------------------------------------------------------------------------
__global__ __launch_bounds__(256) void k2_local(const float* __restrict__ x)
{
    __shared__ __align__(16) float sc[TT * 48];
    int c = blockIdx.x, b = blockIdx.y;
    int tid = threadIdx.x;
    int d  = tid >> 1;
    int nh = tid & 1;

    // front-batched x loads: thread's column of the chunk
    float xv[TT];
    const float* xp = x + (size_t)(b * LL + c * TT) * DD + d;
#pragma unroll
    for (int t = 0; t < TT; t++) xv[t] = xp[t * DD];

    const float4* csrc = (const float4*)(g_coef + (size_t)(b * LL + c * TT) * 48);
    float4* cdst = (float4*)sc;
    for (int i = tid; i < 384; i += 256) cdst[i] = csrc[i];
    __syncthreads();

    u64 h[4];
#pragma unroll
    for (int i = 0; i < 4; i++) h[i] = 0ull;

#pragma unroll 4
    for (int t = 0; t < TT; t++) {
        u64 x2 = pack2(xv[t], xv[t]);
        const ulonglong2* row = (const ulonglong2*)(sc + t * 48);
        ulonglong2 e2a = row[nh * 2],     e2b = row[nh * 2 + 1];
        ulonglong2 w2a = row[4 + nh * 2], w2b = row[5 + nh * 2];
        h[0] = fma2(e2a.x, h[0], mul2(w2a.x, x2));
        h[1] = fma2(e2a.y, h[1], mul2(w2a.y, x2));
        h[2] = fma2(e2b.x, h[2], mul2(w2b.x, x2));
        h[3] = fma2(e2b.y, h[3], mul2(w2b.y, x2));
    }

    // transposed store: Et[b][n][c][d]
    int n0 = nh * 8;
    size_t base = ((size_t)(b * NN + n0) * NC + c) * DD + d;
#pragma unroll
    for (int i = 0; i < 4; i++) {
        float2 v = unpack2(h[i]);
        g_Et[base + (size_t)(2 * i)     * NC * DD] = v.x;
        g_Et[base + (size_t)(2 * i + 1) * NC * DD] = v.y;
    }

    if (tid < 16) {
        float p = 1.f;
#pragma unroll
        for (int t = 0; t < TT; t++) p *= sc[t * 48 + tid];
        g_P[(b * NC + c) * NN + tid] = p;
    }
}

// ---------------------------------------------------------------------------
// K2.5 (merged): inter-chunk combine. One block per (b,n); 128 threads = d.
// Slab Et[b][n][:][:] is bulk-loaded into smem in two 32 KB stages
// (independent coalesced loads -> full MLP), the 128-step serial scan runs
// in smem/registers, carry-ins stream out coalesced to H0t[b][n][c][d].
// ---------------------------------------------------------------------------
__global__ __launch_bounds__(128) void k25_merged()
{
    __shared__ __align__(16) float sE[64 * DD];   // 32 KB stage
    __shared__ float sp[NC];

    int n = blockIdx.x, b = blockIdx.y;
    int d = threadIdx.x;

    sp[d] = g_P[(b * NC + d) * NN + n];           // d doubles as chunk index (NC==128)

    const float* Et  = g_Et  + (size_t)(b * NN + n) * NC * DD;
    float*       H0t = g_H0t + (size_t)(b * NN + n) * NC * DD;

    float h = 0.f;
#pragma unroll
    for (int half = 0; half < 2; half++) {
        // bulk stage load: 64 independent coalesced rows
#pragma unroll
        for (int j = 0; j < 64; j++)
            sE[j * DD + d] = Et[(size_t)(half * 64 + j) * DD + d];
        __syncthreads();
#pragma unroll
        for (int j = 0; j < 64; j++) {
            int c = half * 64 + j;
            H0t[(size_t)c * DD + d] = h;          // fire-and-forget
            h = fmaf(sp[c], h, sE[j * DD + d]);
        }
        __syncthreads();
    }
}

// ---------------------------------------------------------------------------
// K3: final scan with carry-in; y[b,l,d] = sum_n C[l,n]*h[n].
// 256-thread blocks, thread = (d, n-half); carry-in read from transposed
// H0t (coalesced across d); cross-half combine via shfl.
// ---------------------------------------------------------------------------
__global__ __launch_bounds__(256) void k3_scan(const float* __restrict__ x,
                                               float* __restrict__ y)
{
    __shared__ __align__(16) float sc[TT * 48];
    int c = blockIdx.x, b = blockIdx.y;
    int tid = threadIdx.x;
    int d  = tid >> 1;
    int nh = tid & 1;

    float xv[TT];
    const float* xp = x + (size_t)(b * LL + c * TT) * DD + d;
#pragma unroll
    for (int t = 0; t < TT; t++) xv[t] = xp[t * DD];

    const float4* csrc = (const float4*)(g_coef + (size_t)(b * LL + c * TT) * 48);
    float4* cdst = (float4*)sc;
    for (int i = tid; i < 384; i += 256) cdst[i] = csrc[i];

    // carry-in from transposed H0t[b][n][c][d]
    u64 h[4];
    {
        int n0 = nh * 8;
        size_t base = ((size_t)(b * NN + n0) * NC + c) * DD + d;
#pragma unroll
        for (int i = 0; i < 4; i++) {
            float lo = g_H0t[base + (size_t)(2 * i)     * NC * DD];
            float hi = g_H0t[base + (size_t)(2 * i + 1) * NC * DD];
            h[i] = pack2(lo, hi);
        }
    }
    __syncthreads();

    float* yp = y + (size_t)(b * LL + c * TT) * DD + d;

#pragma unroll 4
    for (int t = 0; t < TT; t++) {
        u64 x2 = pack2(xv[t], xv[t]);
        const ulonglong2* row = (const ulonglong2*)(sc + t * 48);
        ulonglong2 e2a = row[nh * 2],     e2b = row[nh * 2 + 1];
        ulonglong2 w2a = row[4 + nh * 2], w2b = row[5 + nh * 2];
        ulonglong2 c2a = row[8 + nh * 2], c2b = row[9 + nh * 2];

        h[0] = fma2(e2a.x, h[0], mul2(w2a.x, x2));
        h[1] = fma2(e2a.y, h[1], mul2(w2a.y, x2));
        h[2] = fma2(e2b.x, h[2], mul2(w2b.x, x2));
        h[3] = fma2(e2b.y, h[3], mul2(w2b.y, x2));

        u64 a0 = 0ull, a1 = 0ull;
        a0 = fma2(c2a.x, h[0], a0);
        a1 = fma2(c2a.y, h[1], a1);
        a0 = fma2(c2b.x, h[2], a0);
        a1 = fma2(c2b.y, h[3], a1);
        float2 p0 = unpack2(a0), p1 = unpack2(a1);
        float part = (p0.x + p0.y) + (p1.x + p1.y);
        float other = __shfl_xor_sync(0xffffffffu, part, 1);
        if (nh == 0) yp[t * DD] = part + other;
    }
}

// ---------------------------------------------------------------------------
extern "C" void kernel_launch(void* const* d_in, const int* in_sizes, int n_in,
                              void* d_out, int out_size)
{
    const float* x  = (const float*)d_in[0];
    const float* A  = (const float*)d_in[1];
    const float* Wb = (const float*)d_in[2];
    const float* bb = (const float*)d_in[3];
    const float* Wc = (const float*)d_in[4];
    const float* bc = (const float*)d_in[5];
    const float* Wd = (const float*)d_in[6];
    const float* bd = (const float*)d_in[7];
    float* y = (float*)d_out;

    k1_coef<<<1024, 64>>>(x, A, Wb, bb, Wc, bc, Wd, bd);

    dim3 grid(NC, BB);
    k2_local<<<grid, 256>>>(x);

    dim3 cgrid(NN, BB);
    k25_merged<<<cgrid, 128>>>();

    k3_scan<<<grid, 256>>>(x, y);
}

// round 14
// speedup vs baseline: 1.5853x; 1.0029x over previous
#include <cuda_runtime.h>

// Problem dimensions (fixed by the reference setup)
#define BB 4
#define LL 4096
#define DD 128
#define NN 16
#define TT 16               // chunk length
#define NC (LL / TT)        // 256 chunks per batch
#define DT_OFF 0.1f

typedef unsigned long long u64;

// Scratch (device globals — no allocation allowed)
__device__ __align__(16) float g_coef[BB * LL * 48];        // per-(b,l): e[16],w[16],C[16]
__device__ __align__(16) float g_Et[BB * NN * NC * DD];     // end states, TRANSPOSED [b][n][c][d]
__device__ __align__(16) float g_H0t[BB * NN * NC * DD];    // carry-ins,  TRANSPOSED [b][n][c][d]
__device__ float g_P[BB * NC * NN];                          // chunk decay products [b][c][n]

// ---------------- packed f32x2 helpers ----------------
__device__ __forceinline__ u64 fma2(u64 a, u64 b, u64 c) {
    u64 d; asm("fma.rn.f32x2 %0, %1, %2, %3;" : "=l"(d) : "l"(a), "l"(b), "l"(c));
    return d;
}
__device__ __forceinline__ u64 mul2(u64 a, u64 b) {
    u64 d; asm("mul.rn.f32x2 %0, %1, %2;" : "=l"(d) : "l"(a), "l"(b));
    return d;
}
__device__ __forceinline__ u64 pack2(float lo, float hi) {
    u64 d;
    asm("mov.b64 %0, {%1, %2};" : "=l"(d)
        : "r"(__float_as_uint(lo)), "r"(__float_as_uint(hi)));
    return d;
}
__device__ __forceinline__ float2 unpack2(u64 v) {
    unsigned int lo, hi;
    asm("mov.b64 {%0, %1}, %2;" : "=r"(lo), "=r"(hi) : "l"(v));
    return make_float2(__uint_as_float(lo), __uint_as_float(hi));
}

// ---------------------------------------------------------------------------
// K1 (j-split): 8 threads per position. Thread q owns 4 COMPLETE dot products
// (rows j = 4q..4q+3 of [Wb;Wc]) over all 128 dims — no reduction shfl needed.
// The shared delta-dot (row 32 = Wd) is split 16 dims/thread + 3-level shfl.
// W bank rotation: index (i+q)&31 puts the 8 lanes on 8 distinct float4-banks.
// Epilogue: q<4 produce e/w for n=4q..4q+3; q>=4 produce C for n=4(q-4)..+3.
// ---------------------------------------------------------------------------
__global__ __launch_bounds__(128) void k1_coef(
    const float* __restrict__ x,
    const float* __restrict__ A,
    const float* __restrict__ Wb, const float* __restrict__ bb,
    const float* __restrict__ Wc, const float* __restrict__ bc,
    const float* __restrict__ Wd, const float* __restrict__ bd)
{
    __shared__ __align__(16) float sW[33 * 128];
    __shared__ float sb[33];
    __shared__ float sA[16];

    int tid = threadIdx.x;
    for (int i = tid; i < 2048; i += 128) {
        sW[i]        = Wb[i];
        sW[2048 + i] = Wc[i];
    }
    sW[4096 + tid] = Wd[tid];
    if (tid < 16) { sb[tid] = bb[tid]; sb[16 + tid] = bc[tid]; sA[tid] = A[tid]; }
    if (tid == 0) sb[32] = bd[0];
    __syncthreads();

    int pos = blockIdx.x * 16 + (tid >> 3);   // (b*L + l), 0..16383
    int q   = tid & 7;                         // j-group / lane role

    const float4* xr = (const float4*)(x + (size_t)pos * DD);
    const float4* W4 = (const float4*)sW;

    // ---- delta partial dot: dims 16q..16q+15 ----
    float accd = 0.f;
    {
        const float4* Wd4 = W4 + 1024;        // row 32 (offset 4096 floats)
#pragma unroll
        for (int ii = 0; ii < 4; ii++) {
            int i = 4 * q + ii;
            float4 xv = xr[i];
            float4 wv = Wd4[i];
            accd = fmaf(xv.w, wv.w, fmaf(xv.z, wv.z,
                   fmaf(xv.y, wv.y, fmaf(xv.x, wv.x, accd))));
        }
    }

    // ---- 4 complete dots (rows j0..j0+3) over all 128 dims ----
    int j0 = q * 4;
    float acc[4] = {0.f, 0.f, 0.f, 0.f};
#pragma unroll 4
    for (int i = 0; i < 32; i++) {
        int ir = (i + q) & 31;                // bank rotation: lanes -> 8 banks
        float4 xv = xr[ir];
#pragma unroll
        for (int jj = 0; jj < 4; jj++) {
            float4 wv = W4[(j0 + jj) * 32 + ir];
            acc[jj] = fmaf(xv.w, wv.w, fmaf(xv.z, wv.z,
                      fmaf(xv.y, wv.y, fmaf(xv.x, wv.x, acc[jj]))));
        }
    }

    // ---- delta reduction across the 8 lanes of this position ----
    accd += __shfl_xor_sync(0xffffffffu, accd, 1);
    accd += __shfl_xor_sync(0xffffffffu, accd, 2);
    accd += __shfl_xor_sync(0xffffffffu, accd, 4);

    float z = accd + sb[32];
    float delta = fmaxf(z, 0.f) + __logf(1.0f + __expf(-fabsf(z))) + DT_OFF;

    float* o = g_coef + (size_t)pos * 48;
    if (q < 4) {
        int n0 = j0;                           // n = 4q..4q+3  (Bp rows)
        float4 eo, wo;
#pragma unroll
        for (int k = 0; k < 4; k++) {
            int n = n0 + k;
            float da = delta * sA[n];
            float e  = __expf(da);
            float em = __expf(-da);
            ((float*)&eo)[k] = e;
            ((float*)&wo)[k] = (1.0f - em) * delta * (acc[k] + sb[n]);
        }
        *(float4*)(o + n0)      = eo;
        *(float4*)(o + 16 + n0) = wo;
    } else {
        int n0 = j0 - 16;                      // n = 4(q-4)..+3  (C rows)
        float4 co;
#pragma unroll
        for (int k = 0; k < 4; k++)
            ((float*)&co)[k] = acc[k] + sb[16 + n0 + k];
        *(float4*)(o + 32 + n0) = co;
    }
}

// ---------------------------------------------------------------------------
// K2: chunk-local scan, h=0 init. 256-thread blocks: thread = (d, n-half).
// Each thread owns 8 n's (4 f32x2 states). End states written TRANSPOSED
// to g_Et[b][n][c][d] (coalesced across d within each n).
// ---------------------------------------------------------------------------
__global__ __launch_bounds__(256) void k2_local(const float* __restrict__ x)
{
    __shared__ __align__(16) float sc[TT * 48];
    int c = blockIdx.x, b = blockIdx.y;
    int tid = threadIdx.x;
    int d  = tid >> 1;
    int nh = tid & 1;

    // front-batched x loads: thread's column of the chunk
    float xv[TT];
    const float* xp = x + (size_t)(b * LL + c * TT) * DD + d;
#pragma unroll
    for (int t = 0; t < TT; t++) xv[t] = xp[t * DD];

    const float4* csrc = (const float4*)(g_coef + (size_t)(b * LL + c * TT) * 48);
    float4* cdst = (float4*)sc;
    if (tid < 192) cdst[tid] = csrc[tid];      // TT*48/4 = 192 float4
    __syncthreads();

    u64 h[4];
#pragma unroll
    for (int i = 0; i < 4; i++) h[i] = 0ull;

#pragma unroll 4
    for (int t = 0; t < TT; t++) {
        u64 x2 = pack2(xv[t], xv[t]);
        const ulonglong2* row = (const ulonglong2*)(sc + t * 48);
        ulonglong2 e2a = row[nh * 2],     e2b = row[nh * 2 + 1];
        ulonglong2 w2a = row[4 + nh * 2], w2b = row[5 + nh * 2];
        h[0] = fma2(e2a.x, h[0], mul2(w2a.x, x2));
        h[1] = fma2(e2a.y, h[1], mul2(w2a.y, x2));
        h[2] = fma2(e2b.x, h[2], mul2(w2b.x, x2));
        h[3] = fma2(e2b.y, h[3], mul2(w2b.y, x2));
    }

    // transposed store: Et[b][n][c][d]
    int n0 = nh * 8;
    size_t base = ((size_t)(b * NN + n0) * NC + c) * DD + d;
#pragma unroll
    for (int i = 0; i < 4; i++) {
        float2 v = unpack2(h[i]);
        g_Et[base + (size_t)(2 * i)     * NC * DD] = v.x;
        g_Et[base + (size_t)(2 * i + 1) * NC * DD] = v.y;
    }

    if (tid < 16) {
        float p = 1.f;
#pragma unroll
        for (int t = 0; t < TT; t++) p *= sc[t * 48 + tid];
        g_P[(b * NC + c) * NN + tid] = p;
    }
}

// ---------------------------------------------------------------------------
// K2.5: inter-chunk combine. One block per (b,n); 128 threads = d.
// Slab Et[b][n][:][:] (128 KB) processed in four 32 KB smem stages
// (independent coalesced loads -> full MLP); the 256-step serial scan runs
// in smem/registers; carry-ins stream out coalesced to H0t[b][n][c][d].
// ---------------------------------------------------------------------------
__global__ __launch_bounds__(128) void k25_merged()
{
    __shared__ __align__(16) float sE[64 * DD];   // 32 KB stage
    __shared__ float sp[NC];

    int n = blockIdx.x, b = blockIdx.y;
    int d = threadIdx.x;

    sp[d]       = g_P[(b * NC + d) * NN + n];
    sp[d + 128] = g_P[(b * NC + d + 128) * NN + n];

    const float* Et  = g_Et  + (size_t)(b * NN + n) * NC * DD;
    float*       H0t = g_H0t + (size_t)(b * NN + n) * NC * DD;

    float h = 0.f;
#pragma unroll
    for (int stage = 0; stage < 4; stage++) {
#pragma unroll
        for (int j = 0; j < 64; j++)
            sE[j * DD + d] = Et[(size_t)(stage * 64 + j) * DD + d];
        __syncthreads();
#pragma unroll
        for (int j = 0; j < 64; j++) {
            int c = stage * 64 + j;
            H0t[(size_t)c * DD + d] = h;          // fire-and-forget
            h = fmaf(sp[c], h, sE[j * DD + d]);
        }
        __syncthreads();
    }
}

// ---------------------------------------------------------------------------
// K3: final scan with carry-in; y[b,l,d] = sum_n C[l,n]*h[n].
// 256-thread blocks, thread = (d, n-half); carry-in read from transposed
// H0t (coalesced across d); cross-half combine via shfl.
// ---------------------------------------------------------------------------
__global__ __launch_bounds__(256) void k3_scan(const float* __restrict__ x,
                                               float* __restrict__ y)
{
    __shared__ __align__(16) float sc[TT * 48];
    int c = blockIdx.x, b = blockIdx.y;
    int tid = threadIdx.x;
    int d  = tid >> 1;
    int nh = tid & 1;

    float xv[TT];
    const float* xp = x + (size_t)(b * LL + c * TT) * DD + d;
#pragma unroll
    for (int t = 0; t < TT; t++) xv[t] = xp[t * DD];

    const float4* csrc = (const float4*)(g_coef + (size_t)(b * LL + c * TT) * 48);
    float4* cdst = (float4*)sc;
    if (tid < 192) cdst[tid] = csrc[tid];

    // carry-in from transposed H0t[b][n][c][d]
    u64 h[4];
    {
        int n0 = nh * 8;
        size_t base = ((size_t)(b * NN + n0) * NC + c) * DD + d;
#pragma unroll
        for (int i = 0; i < 4; i++) {
            float lo = g_H0t[base + (size_t)(2 * i)     * NC * DD];
            float hi = g_H0t[base + (size_t)(2 * i + 1) * NC * DD];
            h[i] = pack2(lo, hi);
        }
    }
    __syncthreads();

    float* yp = y + (size_t)(b * LL + c * TT) * DD + d;

#pragma unroll 4
    for (int t = 0; t < TT; t++) {
        u64 x2 = pack2(xv[t], xv[t]);
        const ulonglong2* row = (const ulonglong2*)(sc + t * 48);
        ulonglong2 e2a = row[nh * 2],     e2b = row[nh * 2 + 1];
        ulonglong2 w2a = row[4 + nh * 2], w2b = row[5 + nh * 2];
        ulonglong2 c2a = row[8 + nh * 2], c2b = row[9 + nh * 2];

        h[0] = fma2(e2a.x, h[0], mul2(w2a.x, x2));
        h[1] = fma2(e2a.y, h[1], mul2(w2a.y, x2));
        h[2] = fma2(e2b.x, h[2], mul2(w2b.x, x2));
        h[3] = fma2(e2b.y, h[3], mul2(w2b.y, x2));

        u64 a0 = 0ull, a1 = 0ull;
        a0 = fma2(c2a.x, h[0], a0);
        a1 = fma2(c2a.y, h[1], a1);
        a0 = fma2(c2b.x, h[2], a0);
        a1 = fma2(c2b.y, h[3], a1);
        float2 p0 = unpack2(a0), p1 = unpack2(a1);
        float part = (p0.x + p0.y) + (p1.x + p1.y);
        float other = __shfl_xor_sync(0xffffffffu, part, 1);
        if (nh == 0) yp[t * DD] = part + other;
    }
}

// ---------------------------------------------------------------------------
extern "C" void kernel_launch(void* const* d_in, const int* in_sizes, int n_in,
                              void* d_out, int out_size)
{
    const float* x  = (const float*)d_in[0];
    const float* A  = (const float*)d_in[1];
    const float* Wb = (const float*)d_in[2];
    const float* bb = (const float*)d_in[3];
    const float* Wc = (const float*)d_in[4];
    const float* bc = (const float*)d_in[5];
    const float* Wd = (const float*)d_in[6];
    const float* bd = (const float*)d_in[7];
    float* y = (float*)d_out;

    k1_coef<<<1024, 128>>>(x, A, Wb, bb, Wc, bc, Wd, bd);

    dim3 grid(NC, BB);
    k2_local<<<grid, 256>>>(x);

    dim3 cgrid(NN, BB);
    k25_merged<<<cgrid, 128>>>();

    k3_scan<<<grid, 256>>>(x, y);
}

// round 15
// speedup vs baseline: 1.6636x; 1.0494x over previous
#include <cuda_runtime.h>

// Problem dimensions (fixed by the reference setup)
#define BB 4
#define LL 4096
#define DD 128
#define NN 16
#define TT 16               // chunk length == positions per GEMM block
#define NC (LL / TT)        // 256 chunks per batch
#define DT_OFF 0.1f

typedef unsigned long long u64;

// Scratch (device globals — no allocation allowed)
__device__ __align__(16) float g_coef[BB * LL * 48];        // per-(b,l): e[16],w[16],C[16]
__device__ __align__(16) float g_Et[BB * NN * NC * DD];     // end states, TRANSPOSED [b][n][c][d]
__device__ __align__(16) float g_H0t[BB * NN * NC * DD];    // carry-ins,  TRANSPOSED [b][n][c][d]
__device__ float g_P[BB * NC * NN];                          // chunk decay products [b][c][n]

// ---------------- packed f32x2 helpers ----------------
__device__ __forceinline__ u64 fma2(u64 a, u64 b, u64 c) {
    u64 d; asm("fma.rn.f32x2 %0, %1, %2, %3;" : "=l"(d) : "l"(a), "l"(b), "l"(c));
    return d;
}
__device__ __forceinline__ u64 mul2(u64 a, u64 b) {
    u64 d; asm("mul.rn.f32x2 %0, %1, %2;" : "=l"(d) : "l"(a), "l"(b));
    return d;
}
__device__ __forceinline__ u64 pack2(float lo, float hi) {
    u64 d;
    asm("mov.b64 %0, {%1, %2};" : "=l"(d)
        : "r"(__float_as_uint(lo)), "r"(__float_as_uint(hi)));
    return d;
}
__device__ __forceinline__ float2 unpack2(u64 v) {
    unsigned int lo, hi;
    asm("mov.b64 {%0, %1}, %2;" : "=r"(lo), "=r"(hi) : "l"(v));
    return make_float2(__uint_as_float(lo), __uint_as_float(hi));
}

// ---------------------------------------------------------------------------
// KM12: merged projection GEMM + chunk-local scan. One block per (c,b),
// 128 threads.
//  Phase G: x chunk -> smem; 8 threads/position j-split GEMM (thread q owns
//           4 complete rows of [Wb;Wc]; delta dot split 16 dims + 3 shfls);
//           coefficients -> smem sc AND g_coef (for K3).
//  Phase S: d-only chunk scan (h=0 init), 8 independent f32x2 chains/thread;
//           end states -> g_Et transposed; decay products -> g_P.
// ---------------------------------------------------------------------------
__global__ __launch_bounds__(128) void km12(
    const float* __restrict__ x,
    const float* __restrict__ A,
    const float* __restrict__ Wb, const float* __restrict__ bb,
    const float* __restrict__ Wc, const float* __restrict__ bc,
    const float* __restrict__ Wd, const float* __restrict__ bd)
{
    __shared__ __align__(16) float sW[33 * 128];   // 16896 B
    __shared__ __align__(16) float sx[TT * DD];    //  8192 B
    __shared__ __align__(16) float sc[TT * 48];    //  3072 B
    __shared__ float sb[33];
    __shared__ float sA[16];

    int tid = threadIdx.x;
    int c = blockIdx.x, b = blockIdx.y;

    // ---- load W / biases / A / x chunk into smem ----
    for (int i = tid; i < 2048; i += 128) {
        sW[i]        = Wb[i];
        sW[2048 + i] = Wc[i];
    }
    sW[4096 + tid] = Wd[tid];
    if (tid < 16) { sb[tid] = bb[tid]; sb[16 + tid] = bc[tid]; sA[tid] = A[tid]; }
    if (tid == 0) sb[32] = bd[0];

    const float4* xg = (const float4*)(x + (size_t)(b * LL + c * TT) * DD);
    float4* sx4 = (float4*)sx;
    sx4[tid]       = xg[tid];
    sx4[tid + 128] = xg[tid + 128];
    sx4[tid + 256] = xg[tid + 256];
    sx4[tid + 384] = xg[tid + 384];
    __syncthreads();

    // ================= Phase G: projection GEMM =================
    {
        int pl = tid >> 3;                     // position in chunk, 0..15
        int q  = tid & 7;                      // j-group / lane role

        const float4* xr = (const float4*)(sx + pl * DD);
        const float4* W4 = (const float4*)sW;

        // delta partial dot: dims 16q..16q+15
        float accd = 0.f;
        {
            const float4* Wd4 = W4 + 1024;     // row 32
#pragma unroll
            for (int ii = 0; ii < 4; ii++) {
                int i = 4 * q + ii;
                float4 xv = xr[i];
                float4 wv = Wd4[i];
                accd = fmaf(xv.w, wv.w, fmaf(xv.z, wv.z,
                       fmaf(xv.y, wv.y, fmaf(xv.x, wv.x, accd))));
            }
        }

        // 4 complete dots (rows j0..j0+3) over all 128 dims
        int j0 = q * 4;
        float acc[4] = {0.f, 0.f, 0.f, 0.f};
#pragma unroll 8
        for (int i = 0; i < 32; i++) {
            int ir = (i + q) & 31;             // bank rotation
            float4 xv = xr[ir];
#pragma unroll
            for (int jj = 0; jj < 4; jj++) {
                float4 wv = W4[(j0 + jj) * 32 + ir];
                acc[jj] = fmaf(xv.w, wv.w, fmaf(xv.z, wv.z,
                          fmaf(xv.y, wv.y, fmaf(xv.x, wv.x, acc[jj]))));
            }
        }

        accd += __shfl_xor_sync(0xffffffffu, accd, 1);
        accd += __shfl_xor_sync(0xffffffffu, accd, 2);
        accd += __shfl_xor_sync(0xffffffffu, accd, 4);

        float z = accd + sb[32];
        float delta = fmaxf(z, 0.f) + __logf(1.0f + __expf(-fabsf(z))) + DT_OFF;

        float* og = g_coef + (size_t)((b * LL + c * TT) + pl) * 48;
        float* os = sc + pl * 48;
        if (q < 4) {
            int n0 = j0;                       // e/w rows
            float4 eo, wo;
#pragma unroll
            for (int k = 0; k < 4; k++) {
                int n = n0 + k;
                float da = delta * sA[n];
                float e  = __expf(da);
                float em = __expf(-da);
                ((float*)&eo)[k] = e;
                ((float*)&wo)[k] = (1.0f - em) * delta * (acc[k] + sb[n]);
            }
            *(float4*)(os + n0)      = eo;
            *(float4*)(os + 16 + n0) = wo;
            *(float4*)(og + n0)      = eo;
            *(float4*)(og + 16 + n0) = wo;
        } else {
            int n0 = j0 - 16;                  // C rows
            float4 co;
#pragma unroll
            for (int k = 0; k < 4; k++)
                ((float*)&co)[k] = acc[k] + sb[16 + n0 + k];
            *(float4*)(os + 32 + n0) = co;
            *(float4*)(og + 32 + n0) = co;
        }
    }
    __syncthreads();

    // ================= Phase S: chunk-local scan =================
    {
        int d = tid;
        u64 h[8];
#pragma unroll
        for (int i = 0; i < 8; i++) h[i] = 0ull;

#pragma unroll
        for (int t = 0; t < TT; t++) {
            float xt = sx[t * DD + d];
            u64 x2 = pack2(xt, xt);
            const ulonglong2* row = (const ulonglong2*)(sc + t * 48);
#pragma unroll
            for (int i = 0; i < 4; i++) {
                ulonglong2 e2 = row[i];
                ulonglong2 w2 = row[4 + i];
                h[2 * i]     = fma2(e2.x, h[2 * i],     mul2(w2.x, x2));
                h[2 * i + 1] = fma2(e2.y, h[2 * i + 1], mul2(w2.y, x2));
            }
        }

        // transposed store: Et[b][n][c][d]
        size_t base = ((size_t)(b * NN) * NC + c) * DD + d;
#pragma unroll
        for (int i = 0; i < 4; i++) {
            float2 v0 = unpack2(h[2 * i]);
            float2 v1 = unpack2(h[2 * i + 1]);
            g_Et[base + (size_t)(4 * i)     * NC * DD] = v0.x;
            g_Et[base + (size_t)(4 * i + 1) * NC * DD] = v0.y;
            g_Et[base + (size_t)(4 * i + 2) * NC * DD] = v1.x;
            g_Et[base + (size_t)(4 * i + 3) * NC * DD] = v1.y;
        }

        if (tid < 16) {
            float p = 1.f;
#pragma unroll
            for (int t = 0; t < TT; t++) p *= sc[t * 48 + tid];
            g_P[(b * NC + c) * NN + tid] = p;
        }
    }
}

// ---------------------------------------------------------------------------
// K2.5: inter-chunk combine. One block per (b,n); 128 threads = d.
// Slab Et[b][n][:][:] (128 KB) processed in four 32 KB smem stages
// (independent coalesced loads -> full MLP); 256-step serial scan in
// smem/registers; carry-ins stream out coalesced to H0t[b][n][c][d].
// ---------------------------------------------------------------------------
__global__ __launch_bounds__(128) void k25_merged()
{
    __shared__ __align__(16) float sE[64 * DD];   // 32 KB stage
    __shared__ float sp[NC];

    int n = blockIdx.x, b = blockIdx.y;
    int d = threadIdx.x;

    sp[d]       = g_P[(b * NC + d) * NN + n];
    sp[d + 128] = g_P[(b * NC + d + 128) * NN + n];

    const float* Et  = g_Et  + (size_t)(b * NN + n) * NC * DD;
    float*       H0t = g_H0t + (size_t)(b * NN + n) * NC * DD;

    float h = 0.f;
#pragma unroll
    for (int stage = 0; stage < 4; stage++) {
#pragma unroll
        for (int j = 0; j < 64; j++)
            sE[j * DD + d] = Et[(size_t)(stage * 64 + j) * DD + d];
        __syncthreads();
#pragma unroll
        for (int j = 0; j < 64; j++) {
            int c = stage * 64 + j;
            H0t[(size_t)c * DD + d] = h;          // fire-and-forget
            h = fmaf(sp[c], h, sE[j * DD + d]);
        }
        __syncthreads();
    }
}

// ---------------------------------------------------------------------------
// K3: final scan with carry-in; y[b,l,d] = sum_n C[l,n]*h[n].
// 256-thread blocks, thread = (d, n-half). Software-pipelined: e/w rows for
// step t+1 are prefetched into registers while step t computes (full unroll).
// x staged through smem. __launch_bounds__(256,4) -> 64-reg budget.
// ---------------------------------------------------------------------------
__global__ __launch_bounds__(256, 4) void k3_scan(const float* __restrict__ x,
                                                  float* __restrict__ y)
{
    __shared__ __align__(16) float sc[TT * 48];
    __shared__ __align__(16) float sx[TT * DD];
    int c = blockIdx.x, b = blockIdx.y;
    int tid = threadIdx.x;
    int d  = tid >> 1;
    int nh = tid & 1;

    // stage x chunk (coalesced float4) and coef rows
    const float4* xg = (const float4*)(x + (size_t)(b * LL + c * TT) * DD);
    float4* sx4 = (float4*)sx;
    sx4[tid]       = xg[tid];
    sx4[tid + 256] = xg[tid + 256];

    const float4* csrc = (const float4*)(g_coef + (size_t)(b * LL + c * TT) * 48);
    float4* cdst = (float4*)sc;
    if (tid < 192) cdst[tid] = csrc[tid];

    // carry-in from transposed H0t[b][n][c][d]
    u64 h[4];
    {
        int n0 = nh * 8;
        size_t base = ((size_t)(b * NN + n0) * NC + c) * DD + d;
#pragma unroll
        for (int i = 0; i < 4; i++) {
            float lo = g_H0t[base + (size_t)(2 * i)     * NC * DD];
            float hi = g_H0t[base + (size_t)(2 * i + 1) * NC * DD];
            h[i] = pack2(lo, hi);
        }
    }
    __syncthreads();

    float* yp = y + (size_t)(b * LL + c * TT) * DD + d;

    const ulonglong2* rows = (const ulonglong2*)sc;   // 12 ulonglong2 per t
    int ro = nh * 2;

    // prefetch step 0's e/w rows
    ulonglong2 pe_a = rows[ro],     pe_b = rows[ro + 1];
    ulonglong2 pw_a = rows[4 + ro], pw_b = rows[5 + ro];

#pragma unroll
    for (int t = 0; t < TT; t++) {
        ulonglong2 e2a = pe_a, e2b = pe_b, w2a = pw_a, w2b = pw_b;
        ulonglong2 c2a = rows[t * 12 + 8 + ro];
        ulonglong2 c2b = rows[t * 12 + 9 + ro];
        if (t + 1 < TT) {                      // prefetch next e/w
            const ulonglong2* nrow = rows + (t + 1) * 12;
            pe_a = nrow[ro];     pe_b = nrow[ro + 1];
            pw_a = nrow[4 + ro]; pw_b = nrow[5 + ro];
        }

        float xt = sx[t * DD + d];
        u64 x2 = pack2(xt, xt);

        h[0] = fma2(e2a.x, h[0], mul2(w2a.x, x2));
        h[1] = fma2(e2a.y, h[1], mul2(w2a.y, x2));
        h[2] = fma2(e2b.x, h[2], mul2(w2b.x, x2));
        h[3] = fma2(e2b.y, h[3], mul2(w2b.y, x2));

        u64 a0 = 0ull, a1 = 0ull;
        a0 = fma2(c2a.x, h[0], a0);
        a1 = fma2(c2a.y, h[1], a1);
        a0 = fma2(c2b.x, h[2], a0);
        a1 = fma2(c2b.y, h[3], a1);
        float2 p0 = unpack2(a0), p1 = unpack2(a1);
        float part = (p0.x + p0.y) + (p1.x + p1.y);
        float other = __shfl_xor_sync(0xffffffffu, part, 1);
        if (nh == 0) yp[t * DD] = part + other;
    }
}

// ---------------------------------------------------------------------------
extern "C" void kernel_launch(void* const* d_in, const int* in_sizes, int n_in,
                              void* d_out, int out_size)
{
    const float* x  = (const float*)d_in[0];
    const float* A  = (const float*)d_in[1];
    const float* Wb = (const float*)d_in[2];
    const float* bb = (const float*)d_in[3];
    const float* Wc = (const float*)d_in[4];
    const float* bc = (const float*)d_in[5];
    const float* Wd = (const float*)d_in[6];
    const float* bd = (const float*)d_in[7];
    float* y = (float*)d_out;

    dim3 grid(NC, BB);
    km12<<<grid, 128>>>(x, A, Wb, bb, Wc, bc, Wd, bd);

    dim3 cgrid(NN, BB);
    k25_merged<<<cgrid, 128>>>();

    k3_scan<<<grid, 256>>>(x, y);
}